// round 12
// baseline (speedup 1.0000x reference)
#include <cuda_runtime.h>
#include <cuda_fp16.h>
#include <cstdint>

#define TOKENS 8192
#define DIN    4096
#define DOUT   16384

// Scratch (device globals are the sanctioned scratch mechanism)
__device__ __half g_xn[(size_t)TOKENS * DIN];   // layernormed x, fp16 (64 MB)
__device__ __half g_ws[(size_t)DOUT * DIN];     // sign(W), fp16 (128 MB)

__device__ __forceinline__ uint32_t smem_u32(const void* p) {
    uint32_t a;
    asm("{ .reg .u64 t; cvta.to.shared.u64 t, %1; cvt.u32.u64 %0, t; }"
        : "=r"(a) : "l"(p));
    return a;
}

__device__ __forceinline__ float sgnf(float a) {
    return (a > 0.f) ? 1.f : ((a < 0.f) ? -1.f : 0.f);
}

// ---------------------------------------------------------------------------
// Kernel 1 (fused prep): per-block layernorm row, then grid-stride sign(W)
// ---------------------------------------------------------------------------
__global__ __launch_bounds__(256) void prep_kernel(const float* __restrict__ x,
                                                   const float4* __restrict__ w) {
    int row = blockIdx.x;
    {
        const float4* xr = (const float4*)(x + (size_t)row * DIN);
        float4 v[4];
        float s = 0.f, ss = 0.f;
#pragma unroll
        for (int i = 0; i < 4; i++) {
            v[i] = xr[threadIdx.x + i * 256];
            s  += v[i].x + v[i].y + v[i].z + v[i].w;
            ss += v[i].x * v[i].x + v[i].y * v[i].y + v[i].z * v[i].z + v[i].w * v[i].w;
        }
#pragma unroll
        for (int o = 16; o > 0; o >>= 1) {
            s  += __shfl_xor_sync(0xFFFFFFFFu, s, o);
            ss += __shfl_xor_sync(0xFFFFFFFFu, ss, o);
        }
        __shared__ float sh[18];
        int wid = threadIdx.x >> 5, lane = threadIdx.x & 31;
        if (lane == 0) { sh[wid] = s; sh[8 + wid] = ss; }
        __syncthreads();
        if (threadIdx.x == 0) {
            float S = 0.f, SS = 0.f;
#pragma unroll
            for (int i = 0; i < 8; i++) { S += sh[i]; SS += sh[8 + i]; }
            float mean = S * (1.f / DIN);
            float var  = fmaxf((SS - S * mean) * (1.f / (DIN - 1)), 0.f);
            sh[16] = mean;
            sh[17] = 1.f / (sqrtf(var) + 1e-5f);
        }
        __syncthreads();
        float mean = sh[16], inv = sh[17];
        __half2* orow = (__half2*)(g_xn + (size_t)row * DIN);
#pragma unroll
        for (int i = 0; i < 4; i++) {
            int j = threadIdx.x + i * 256;
            orow[j * 2 + 0] = __floats2half2_rn((v[i].x - mean) * inv, (v[i].y - mean) * inv);
            orow[j * 2 + 1] = __floats2half2_rn((v[i].z - mean) * inv, (v[i].w - mean) * inv);
        }
    }
    {
        size_t total = (size_t)DOUT * DIN / 4;
        size_t stride = (size_t)gridDim.x * 256;
        __half2* o = (__half2*)g_ws;
        for (size_t i = (size_t)blockIdx.x * 256 + threadIdx.x; i < total; i += stride) {
            float4 v = w[i];
            o[2 * i + 0] = __floats2half2_rn(sgnf(v.x), sgnf(v.y));
            o[2 * i + 1] = __floats2half2_rn(sgnf(v.z), sgnf(v.w));
        }
    }
}

// ---------------------------------------------------------------------------
// Kernel 2: persistent HMMA GEMM (R11 structure). CTA = 128 threads (2x2
//   warps), tile 128x128x64, warp tile 64x64, 3-stage cp.async, 2 CTAs/SM.
//   cp.async stream spread as FOUR 4-deep bursts (one per kk section);
//   prefetch continuous across tile boundaries; stage idx = mod-3 counters.
// ---------------------------------------------------------------------------
constexpr int BM = 128, BN = 128, BK = 64;
constexpr int NK = DIN / BK;                 // 64 K-chunks per tile
constexpr int ASZ = BM * BK * 2;             // 16 KB
constexpr int BSZ = BN * BK * 2;             // 16 KB
constexpr int STG = ASZ + BSZ;               // 32 KB per stage
constexpr int NSTAGE = 3;
constexpr int SMEM_TOTAL = NSTAGE * STG;     // 96 KB (x2 CTAs = 192 KB/SM)
constexpr int CTA_THREADS = 128;
constexpr int NTILES = (TOKENS / BM) * (DOUT / BN);   // 8192

__device__ __forceinline__ void ldmx4(uint32_t* r, uint32_t addr) {
    asm volatile("ldmatrix.sync.aligned.m8n8.x4.shared.b16 {%0,%1,%2,%3}, [%4];"
                 : "=r"(r[0]), "=r"(r[1]), "=r"(r[2]), "=r"(r[3]) : "r"(addr));
}

__device__ __forceinline__ void mma16816(float* c, const uint32_t* a, const uint32_t* b) {
    asm volatile(
        "mma.sync.aligned.m16n8k16.row.col.f32.f16.f16.f32 "
        "{%0,%1,%2,%3}, {%4,%5,%6,%7}, {%8,%9}, {%0,%1,%2,%3};"
        : "+f"(c[0]), "+f"(c[1]), "+f"(c[2]), "+f"(c[3])
        : "r"(a[0]), "r"(a[1]), "r"(a[2]), "r"(a[3]), "r"(b[0]), "r"(b[1]));
}

// quarter-stage bursts: 4 cp.async per thread each
// A half h (h=0,1): rows/chunks g in [h*512, h*512+512)
__device__ __forceinline__ void load_A_half(uint32_t sb, int buf, int kc,
                                            const __half* Ag, int tid, int h) {
    uint32_t base = sb + buf * STG;
    int k0 = kc * BK;
#pragma unroll
    for (int i = 0; i < 4; i++) {
        int g = tid + (h * 4 + i) * CTA_THREADS;
        int row = g >> 3, c = g & 7;
        const void* src = Ag + (size_t)row * DIN + k0 + c * 8;
        uint32_t dst = base + row * 128 + ((c ^ (row & 7)) << 4);
        asm volatile("cp.async.cg.shared.global [%0], [%1], 16;" :: "r"(dst), "l"(src) : "memory");
    }
}

__device__ __forceinline__ void load_B_half(uint32_t sb, int buf, int kc,
                                            const __half* Bg, int tid, int h) {
    uint32_t base = sb + buf * STG + ASZ;
    int k0 = kc * BK;
#pragma unroll
    for (int i = 0; i < 4; i++) {
        int g = tid + (h * 4 + i) * CTA_THREADS;
        int row = g >> 3, c = g & 7;
        const void* src = Bg + (size_t)row * DIN + k0 + c * 8;
        uint32_t dst = base + row * 128 + ((c ^ (row & 7)) << 4);
        asm volatile("cp.async.cg.shared.global [%0], [%1], 16;" :: "r"(dst), "l"(src) : "memory");
    }
}

__global__ __launch_bounds__(CTA_THREADS, 2)
void gemm_kernel(const float* __restrict__ bias, float* __restrict__ out) {
    extern __shared__ char smem[];
    uint32_t sb = smem_u32(smem);
    int tid = threadIdx.x, wid = tid >> 5, lane = tid & 31;
    int wm = wid & 1;        // 2 warps along M (64 rows each)
    int wn = wid >> 1;       // 2 warps along N (64 cols each)
    int bid = blockIdx.x, nblk = gridDim.x;

    // A ldmatrix lane address components
    int arow = wm * 64 + (lane & 15);
    int ahalf = lane >> 4;
    int axm = arow & 7;
    uint32_t aoff = (uint32_t)arow * 128;
    // B ldmatrix lane address components
    int bgp = lane >> 3, bj = lane & 7;
    int brow = wn * 64 + ((bgp >> 1) << 3) + bj;
    int bhalf = bgp & 1;
    int bxm = brow & 7;
    uint32_t boff = (uint32_t)brow * 128;

    int ntile_cta = (NTILES - bid + nblk - 1) / nblk;
    if (ntile_cta <= 0) return;

    int buf = 0;        // stage holding current kc's data
    int pbuf = 2;       // stage that prefetch (kc+2) writes into

    // prologue: fill stages 0,1 with tile0 kc0,kc1
    {
        const __half* Ag0 = g_xn + (size_t)(bid & 63) * BM * DIN;
        const __half* Bg0 = g_ws + (size_t)(bid >> 6) * BN * DIN;
        load_A_half(sb, 0, 0, Ag0, tid, 0);
        load_A_half(sb, 0, 0, Ag0, tid, 1);
        load_B_half(sb, 0, 0, Bg0, tid, 0);
        load_B_half(sb, 0, 0, Bg0, tid, 1);
        asm volatile("cp.async.commit_group;" ::: "memory");
        load_A_half(sb, 1, 1, Ag0, tid, 0);
        load_A_half(sb, 1, 1, Ag0, tid, 1);
        load_B_half(sb, 1, 1, Bg0, tid, 0);
        load_B_half(sb, 1, 1, Bg0, tid, 1);
        asm volatile("cp.async.commit_group;" ::: "memory");
    }

    for (int it = 0; it < ntile_cta; it++) {
        int t = bid + it * nblk;
        int m0 = (t & 63) * BM;
        int n0 = (t >> 6) * BN;
        const __half* Ag = g_xn + (size_t)(t & 63) * BM * DIN;
        const __half* Bg = g_ws + (size_t)(t >> 6) * BN * DIN;

        bool has_next = (it + 1 < ntile_cta);
        int tn = t + nblk;
        if (tn >= NTILES) tn = t;
        const __half* AgN = g_xn + (size_t)(tn & 63) * BM * DIN;
        const __half* BgN = g_ws + (size_t)(tn >> 6) * BN * DIN;

        float acc[4][8][4];
#pragma unroll
        for (int i = 0; i < 4; i++)
#pragma unroll
            for (int j = 0; j < 8; j++)
#pragma unroll
                for (int q = 0; q < 4; q++) acc[i][j][q] = 0.f;

        for (int kc = 0; kc < NK; kc++) {
            asm volatile("cp.async.wait_group 1;" ::: "memory");
            __syncthreads();

            uint32_t abase = sb + buf * STG + aoff;
            uint32_t bbase = sb + buf * STG + ASZ + boff;

            bool pf_cur = (kc < NK - 2);
            bool pf_nxt = (!pf_cur) && has_next;
            int pkc_c = kc + 2;
            int pkc_n = kc + 2 - NK;
            const __half* pA = pf_cur ? Ag : AgN;
            const __half* pB = pf_cur ? Bg : BgN;
            int pkc = pf_cur ? pkc_c : pkc_n;
            bool pf = pf_cur || pf_nxt;

            uint32_t afr[4][4], bfr[4][4];

            // ---- kk=0: LDSMs, A-burst half0, MMAs
#pragma unroll
            for (int mt = 0; mt < 4; mt++)
                ldmx4(afr[mt], abase + mt * 2048 + ((ahalf ^ axm) << 4));
#pragma unroll
            for (int np = 0; np < 4; np++)
                ldmx4(bfr[np], bbase + np * 2048 + ((bhalf ^ bxm) << 4));

            if (pf) load_A_half(sb, pbuf, pkc, pA, tid, 0);

#pragma unroll
            for (int mt = 0; mt < 4; mt++)
#pragma unroll
                for (int nt = 0; nt < 8; nt++)
                    mma16816(acc[mt][nt], afr[mt], &bfr[nt >> 1][(nt & 1) * 2]);

            // ---- kk=1: LDSMs, A-burst half1, MMAs
#pragma unroll
            for (int mt = 0; mt < 4; mt++)
                ldmx4(afr[mt], abase + mt * 2048 + (((2 + ahalf) ^ axm) << 4));
#pragma unroll
            for (int np = 0; np < 4; np++)
                ldmx4(bfr[np], bbase + np * 2048 + (((2 + bhalf) ^ bxm) << 4));

            if (pf) load_A_half(sb, pbuf, pkc, pA, tid, 1);

#pragma unroll
            for (int mt = 0; mt < 4; mt++)
#pragma unroll
                for (int nt = 0; nt < 8; nt++)
                    mma16816(acc[mt][nt], afr[mt], &bfr[nt >> 1][(nt & 1) * 2]);

            // ---- kk=2: LDSMs, B-burst half0, MMAs
#pragma unroll
            for (int mt = 0; mt < 4; mt++)
                ldmx4(afr[mt], abase + mt * 2048 + (((4 + ahalf) ^ axm) << 4));
#pragma unroll
            for (int np = 0; np < 4; np++)
                ldmx4(bfr[np], bbase + np * 2048 + (((4 + bhalf) ^ bxm) << 4));

            if (pf) load_B_half(sb, pbuf, pkc, pB, tid, 0);

#pragma unroll
            for (int mt = 0; mt < 4; mt++)
#pragma unroll
                for (int nt = 0; nt < 8; nt++)
                    mma16816(acc[mt][nt], afr[mt], &bfr[nt >> 1][(nt & 1) * 2]);

            // ---- kk=3: LDSMs, B-burst half1 + commit, MMAs
#pragma unroll
            for (int mt = 0; mt < 4; mt++)
                ldmx4(afr[mt], abase + mt * 2048 + (((6 + ahalf) ^ axm) << 4));
#pragma unroll
            for (int np = 0; np < 4; np++)
                ldmx4(bfr[np], bbase + np * 2048 + (((6 + bhalf) ^ bxm) << 4));

            if (pf) load_B_half(sb, pbuf, pkc, pB, tid, 1);
            asm volatile("cp.async.commit_group;" ::: "memory");

#pragma unroll
            for (int mt = 0; mt < 4; mt++)
#pragma unroll
                for (int nt = 0; nt < 8; nt++)
                    mma16816(acc[mt][nt], afr[mt], &bfr[nt >> 1][(nt & 1) * 2]);

            buf  = (buf == NSTAGE - 1)  ? 0 : buf + 1;
            pbuf = (pbuf == NSTAGE - 1) ? 0 : pbuf + 1;
        }

        // epilogue: bias hoisted (8 loads/thread), streaming stores
        float2 bv[8];
#pragma unroll
        for (int nt = 0; nt < 8; nt++) {
            int col = n0 + wn * 64 + nt * 8 + 2 * (lane & 3);
            asm volatile("ld.global.nc.v2.f32 {%0,%1}, [%2];"
                         : "=f"(bv[nt].x), "=f"(bv[nt].y) : "l"(bias + col));
        }
#pragma unroll
        for (int mt = 0; mt < 4; mt++) {
#pragma unroll
            for (int nt = 0; nt < 8; nt++) {
                int row = m0 + wm * 64 + mt * 16 + (lane >> 2);
                int col = n0 + wn * 64 + nt * 8 + 2 * (lane & 3);
                float* p0 = out + (size_t)row * DOUT + col;
                float* p1 = out + (size_t)(row + 8) * DOUT + col;
                asm volatile("st.global.cs.v2.f32 [%0], {%1,%2};"
                             :: "l"(p0), "f"(acc[mt][nt][0] + bv[nt].x), "f"(acc[mt][nt][1] + bv[nt].y)
                             : "memory");
                asm volatile("st.global.cs.v2.f32 [%0], {%1,%2};"
                             :: "l"(p1), "f"(acc[mt][nt][2] + bv[nt].x), "f"(acc[mt][nt][3] + bv[nt].y)
                             : "memory");
            }
        }
    }
}

// ---------------------------------------------------------------------------
// kernel_launch
// ---------------------------------------------------------------------------
extern "C" void kernel_launch(void* const* d_in, const int* in_sizes, int n_in,
                              void* d_out, int out_size) {
    const float* x    = (const float*)d_in[0];
    const float* w    = (const float*)d_in[1];
    const float* bias = (const float*)d_in[2];
    float* out = (float*)d_out;

    static int nsm = 0;
    if (nsm == 0) {
        cudaDeviceGetAttribute(&nsm, cudaDevAttrMultiProcessorCount, 0);
        cudaFuncSetAttribute(gemm_kernel, cudaFuncAttributeMaxDynamicSharedMemorySize, SMEM_TOTAL);
    }

    prep_kernel<<<TOKENS, 256>>>(x, (const float4*)w);
    gemm_kernel<<<2 * nsm, CTA_THREADS, SMEM_TOTAL>>>(bias, out);
}

// round 13
// speedup vs baseline: 1.0786x; 1.0786x over previous
#include <cuda_runtime.h>
#include <cuda_fp16.h>
#include <cstdint>

#define TOKENS 8192
#define DIN    4096
#define DOUT   16384

// Scratch (device globals are the sanctioned scratch mechanism)
__device__ __half g_xn[(size_t)TOKENS * DIN];   // layernormed x, fp16 (64 MB)
__device__ __half g_ws[(size_t)DOUT * DIN];     // sign(W), fp16 (128 MB)

__device__ __forceinline__ uint32_t smem_u32(const void* p) {
    uint32_t a;
    asm("{ .reg .u64 t; cvta.to.shared.u64 t, %1; cvt.u32.u64 %0, t; }"
        : "=r"(a) : "l"(p));
    return a;
}

__device__ __forceinline__ float sgnf(float a) {
    return (a > 0.f) ? 1.f : ((a < 0.f) ? -1.f : 0.f);
}

// ---------------------------------------------------------------------------
// Kernel 1 (fused prep): per-block layernorm row, then grid-stride sign(W)
// ---------------------------------------------------------------------------
__global__ __launch_bounds__(256) void prep_kernel(const float* __restrict__ x,
                                                   const float4* __restrict__ w) {
    int row = blockIdx.x;
    {
        const float4* xr = (const float4*)(x + (size_t)row * DIN);
        float4 v[4];
        float s = 0.f, ss = 0.f;
#pragma unroll
        for (int i = 0; i < 4; i++) {
            v[i] = xr[threadIdx.x + i * 256];
            s  += v[i].x + v[i].y + v[i].z + v[i].w;
            ss += v[i].x * v[i].x + v[i].y * v[i].y + v[i].z * v[i].z + v[i].w * v[i].w;
        }
#pragma unroll
        for (int o = 16; o > 0; o >>= 1) {
            s  += __shfl_xor_sync(0xFFFFFFFFu, s, o);
            ss += __shfl_xor_sync(0xFFFFFFFFu, ss, o);
        }
        __shared__ float sh[18];
        int wid = threadIdx.x >> 5, lane = threadIdx.x & 31;
        if (lane == 0) { sh[wid] = s; sh[8 + wid] = ss; }
        __syncthreads();
        if (threadIdx.x == 0) {
            float S = 0.f, SS = 0.f;
#pragma unroll
            for (int i = 0; i < 8; i++) { S += sh[i]; SS += sh[8 + i]; }
            float mean = S * (1.f / DIN);
            float var  = fmaxf((SS - S * mean) * (1.f / (DIN - 1)), 0.f);
            sh[16] = mean;
            sh[17] = 1.f / (sqrtf(var) + 1e-5f);
        }
        __syncthreads();
        float mean = sh[16], inv = sh[17];
        __half2* orow = (__half2*)(g_xn + (size_t)row * DIN);
#pragma unroll
        for (int i = 0; i < 4; i++) {
            int j = threadIdx.x + i * 256;
            orow[j * 2 + 0] = __floats2half2_rn((v[i].x - mean) * inv, (v[i].y - mean) * inv);
            orow[j * 2 + 1] = __floats2half2_rn((v[i].z - mean) * inv, (v[i].w - mean) * inv);
        }
    }
    {
        size_t total = (size_t)DOUT * DIN / 4;
        size_t stride = (size_t)gridDim.x * 256;
        __half2* o = (__half2*)g_ws;
        for (size_t i = (size_t)blockIdx.x * 256 + threadIdx.x; i < total; i += stride) {
            float4 v = w[i];
            o[2 * i + 0] = __floats2half2_rn(sgnf(v.x), sgnf(v.y));
            o[2 * i + 1] = __floats2half2_rn(sgnf(v.z), sgnf(v.w));
        }
    }
}

// ---------------------------------------------------------------------------
// Kernel 2: persistent HMMA GEMM (R11 structure, exact). CTA = 128 threads
//   (2x2 warps), tile 128x128x64, warp tile 64x64, 3-stage cp.async,
//   2 CTAs/SM. Two 8-deep cp.async bursts per kc (A after kk0 LDSMs,
//   B after kk1 LDSMs, commit at kk1); prefetch continuous across tiles;
//   stage idx = mod-3 counters. Epilogue bias hoisted per tile.
// ---------------------------------------------------------------------------
constexpr int BM = 128, BN = 128, BK = 64;
constexpr int NK = DIN / BK;                 // 64 K-chunks per tile
constexpr int ASZ = BM * BK * 2;             // 16 KB
constexpr int BSZ = BN * BK * 2;             // 16 KB
constexpr int STG = ASZ + BSZ;               // 32 KB per stage
constexpr int NSTAGE = 3;
constexpr int SMEM_TOTAL = NSTAGE * STG;     // 96 KB (x2 CTAs = 192 KB/SM)
constexpr int CTA_THREADS = 128;
constexpr int NTILES = (TOKENS / BM) * (DOUT / BN);   // 8192

__device__ __forceinline__ void ldmx4(uint32_t* r, uint32_t addr) {
    asm volatile("ldmatrix.sync.aligned.m8n8.x4.shared.b16 {%0,%1,%2,%3}, [%4];"
                 : "=r"(r[0]), "=r"(r[1]), "=r"(r[2]), "=r"(r[3]) : "r"(addr));
}

__device__ __forceinline__ void mma16816(float* c, const uint32_t* a, const uint32_t* b) {
    asm volatile(
        "mma.sync.aligned.m16n8k16.row.col.f32.f16.f16.f32 "
        "{%0,%1,%2,%3}, {%4,%5,%6,%7}, {%8,%9}, {%0,%1,%2,%3};"
        : "+f"(c[0]), "+f"(c[1]), "+f"(c[2]), "+f"(c[3])
        : "r"(a[0]), "r"(a[1]), "r"(a[2]), "r"(a[3]), "r"(b[0]), "r"(b[1]));
}

__device__ __forceinline__ void load_stage_A(uint32_t sb, int buf, int kc,
                                             const __half* Ag, int tid) {
    uint32_t base = sb + buf * STG;
    int k0 = kc * BK;
#pragma unroll
    for (int i = 0; i < 8; i++) {
        int g = tid + i * CTA_THREADS;
        int row = g >> 3, c = g & 7;
        const void* src = Ag + (size_t)row * DIN + k0 + c * 8;
        uint32_t dst = base + row * 128 + ((c ^ (row & 7)) << 4);
        asm volatile("cp.async.cg.shared.global [%0], [%1], 16;" :: "r"(dst), "l"(src) : "memory");
    }
}

__device__ __forceinline__ void load_stage_B(uint32_t sb, int buf, int kc,
                                             const __half* Bg, int tid) {
    uint32_t base = sb + buf * STG + ASZ;
    int k0 = kc * BK;
#pragma unroll
    for (int i = 0; i < 8; i++) {
        int g = tid + i * CTA_THREADS;
        int row = g >> 3, c = g & 7;
        const void* src = Bg + (size_t)row * DIN + k0 + c * 8;
        uint32_t dst = base + row * 128 + ((c ^ (row & 7)) << 4);
        asm volatile("cp.async.cg.shared.global [%0], [%1], 16;" :: "r"(dst), "l"(src) : "memory");
    }
}

__global__ __launch_bounds__(CTA_THREADS, 2)
void gemm_kernel(const float* __restrict__ bias, float* __restrict__ out) {
    extern __shared__ char smem[];
    uint32_t sb = smem_u32(smem);
    int tid = threadIdx.x, wid = tid >> 5, lane = tid & 31;
    int wm = wid & 1;        // 2 warps along M (64 rows each)
    int wn = wid >> 1;       // 2 warps along N (64 cols each)
    int bid = blockIdx.x, nblk = gridDim.x;

    // A ldmatrix lane address components
    int arow = wm * 64 + (lane & 15);
    int ahalf = lane >> 4;
    int axm = arow & 7;
    uint32_t aoff = (uint32_t)arow * 128;
    // B ldmatrix lane address components
    int bgp = lane >> 3, bj = lane & 7;
    int brow = wn * 64 + ((bgp >> 1) << 3) + bj;
    int bhalf = bgp & 1;
    int bxm = brow & 7;
    uint32_t boff = (uint32_t)brow * 128;

    int ntile_cta = (NTILES - bid + nblk - 1) / nblk;
    if (ntile_cta <= 0) return;

    // stage counters (increment-mod-3, no division in the loop)
    int buf = 0;        // stage holding current kc's data
    int pbuf = 2;       // stage that prefetch (kc+2) writes into

    // prologue: fill stages 0,1 with tile0 kc0,kc1
    {
        const __half* Ag0 = g_xn + (size_t)(bid & 63) * BM * DIN;
        const __half* Bg0 = g_ws + (size_t)(bid >> 6) * BN * DIN;
        load_stage_A(sb, 0, 0, Ag0, tid);
        load_stage_B(sb, 0, 0, Bg0, tid);
        asm volatile("cp.async.commit_group;" ::: "memory");
        load_stage_A(sb, 1, 1, Ag0, tid);
        load_stage_B(sb, 1, 1, Bg0, tid);
        asm volatile("cp.async.commit_group;" ::: "memory");
    }

    for (int it = 0; it < ntile_cta; it++) {
        int t = bid + it * nblk;
        int m0 = (t & 63) * BM;
        int n0 = (t >> 6) * BN;
        const __half* Ag = g_xn + (size_t)(t & 63) * BM * DIN;
        const __half* Bg = g_ws + (size_t)(t >> 6) * BN * DIN;

        // next-tile pointers, computed ONCE per tile
        bool has_next = (it + 1 < ntile_cta);
        int tn = t + nblk;
        if (tn >= NTILES) tn = t;                // clamp (unused when !has_next)
        const __half* AgN = g_xn + (size_t)(tn & 63) * BM * DIN;
        const __half* BgN = g_ws + (size_t)(tn >> 6) * BN * DIN;

        float acc[4][8][4];
#pragma unroll
        for (int i = 0; i < 4; i++)
#pragma unroll
            for (int j = 0; j < 8; j++)
#pragma unroll
                for (int q = 0; q < 4; q++) acc[i][j][q] = 0.f;

        for (int kc = 0; kc < NK; kc++) {
            asm volatile("cp.async.wait_group 1;" ::: "memory");
            __syncthreads();

            uint32_t abase = sb + buf * STG + aoff;
            uint32_t bbase = sb + buf * STG + ASZ + boff;

            // prefetch routing: common case = current tile (identical to R9)
            bool pf_cur = (kc < NK - 2);
            bool pf_nxt = (!pf_cur) && has_next;
            int pkc_n = kc + 2 - NK;             // 0 or 1 in the peel region

            uint32_t afr[4][4], bfr[4][4];

            // kk=0 LDSMs, then A-prefetch burst, then kk=0 MMAs
#pragma unroll
            for (int mt = 0; mt < 4; mt++)
                ldmx4(afr[mt], abase + mt * 2048 + ((ahalf ^ axm) << 4));
#pragma unroll
            for (int np = 0; np < 4; np++)
                ldmx4(bfr[np], bbase + np * 2048 + ((bhalf ^ bxm) << 4));

            if (pf_cur)      load_stage_A(sb, pbuf, kc + 2, Ag, tid);
            else if (pf_nxt) load_stage_A(sb, pbuf, pkc_n, AgN, tid);

#pragma unroll
            for (int mt = 0; mt < 4; mt++)
#pragma unroll
                for (int nt = 0; nt < 8; nt++)
                    mma16816(acc[mt][nt], afr[mt], &bfr[nt >> 1][(nt & 1) * 2]);

            // kk=1 LDSMs, then B-prefetch burst + commit, then kk=1 MMAs
#pragma unroll
            for (int mt = 0; mt < 4; mt++)
                ldmx4(afr[mt], abase + mt * 2048 + (((2 + ahalf) ^ axm) << 4));
#pragma unroll
            for (int np = 0; np < 4; np++)
                ldmx4(bfr[np], bbase + np * 2048 + (((2 + bhalf) ^ bxm) << 4));

            if (pf_cur)      load_stage_B(sb, pbuf, kc + 2, Bg, tid);
            else if (pf_nxt) load_stage_B(sb, pbuf, pkc_n, BgN, tid);
            asm volatile("cp.async.commit_group;" ::: "memory");

#pragma unroll
            for (int mt = 0; mt < 4; mt++)
#pragma unroll
                for (int nt = 0; nt < 8; nt++)
                    mma16816(acc[mt][nt], afr[mt], &bfr[nt >> 1][(nt & 1) * 2]);

            // kk = 2..3
#pragma unroll
            for (int kk = 2; kk < 4; kk++) {
#pragma unroll
                for (int mt = 0; mt < 4; mt++) {
                    int ch = kk * 2 + ahalf;
                    ldmx4(afr[mt], abase + mt * 2048 + ((ch ^ axm) << 4));
                }
#pragma unroll
                for (int np = 0; np < 4; np++) {
                    int ch = kk * 2 + bhalf;
                    ldmx4(bfr[np], bbase + np * 2048 + ((ch ^ bxm) << 4));
                }
#pragma unroll
                for (int mt = 0; mt < 4; mt++)
#pragma unroll
                    for (int nt = 0; nt < 8; nt++)
                        mma16816(acc[mt][nt], afr[mt], &bfr[nt >> 1][(nt & 1) * 2]);
            }

            // advance stage counters (SEL, no division)
            buf  = (buf == NSTAGE - 1)  ? 0 : buf + 1;
            pbuf = (pbuf == NSTAGE - 1) ? 0 : pbuf + 1;
        }

        // epilogue: bias hoisted (8 loads/thread/tile), streaming stores
        float2 bv[8];
#pragma unroll
        for (int nt = 0; nt < 8; nt++) {
            int col = n0 + wn * 64 + nt * 8 + 2 * (lane & 3);
            asm volatile("ld.global.nc.v2.f32 {%0,%1}, [%2];"
                         : "=f"(bv[nt].x), "=f"(bv[nt].y) : "l"(bias + col));
        }
#pragma unroll
        for (int mt = 0; mt < 4; mt++) {
#pragma unroll
            for (int nt = 0; nt < 8; nt++) {
                int row = m0 + wm * 64 + mt * 16 + (lane >> 2);
                int col = n0 + wn * 64 + nt * 8 + 2 * (lane & 3);
                float* p0 = out + (size_t)row * DOUT + col;
                float* p1 = out + (size_t)(row + 8) * DOUT + col;
                asm volatile("st.global.cs.v2.f32 [%0], {%1,%2};"
                             :: "l"(p0), "f"(acc[mt][nt][0] + bv[nt].x), "f"(acc[mt][nt][1] + bv[nt].y)
                             : "memory");
                asm volatile("st.global.cs.v2.f32 [%0], {%1,%2};"
                             :: "l"(p1), "f"(acc[mt][nt][2] + bv[nt].x), "f"(acc[mt][nt][3] + bv[nt].y)
                             : "memory");
            }
        }
    }
}

// ---------------------------------------------------------------------------
// kernel_launch
// ---------------------------------------------------------------------------
extern "C" void kernel_launch(void* const* d_in, const int* in_sizes, int n_in,
                              void* d_out, int out_size) {
    const float* x    = (const float*)d_in[0];
    const float* w    = (const float*)d_in[1];
    const float* bias = (const float*)d_in[2];
    float* out = (float*)d_out;

    static int nsm = 0;
    if (nsm == 0) {
        cudaDeviceGetAttribute(&nsm, cudaDevAttrMultiProcessorCount, 0);
        cudaFuncSetAttribute(gemm_kernel, cudaFuncAttributeMaxDynamicSharedMemorySize, SMEM_TOTAL);
    }

    prep_kernel<<<TOKENS, 256>>>(x, (const float4*)w);
    gemm_kernel<<<2 * nsm, CTA_THREADS, SMEM_TOTAL>>>(bias, out);
}

// round 14
// speedup vs baseline: 1.0797x; 1.0010x over previous
#include <cuda_runtime.h>
#include <cuda_fp16.h>
#include <cstdint>

#define TOKENS 8192
#define DIN    4096
#define DOUT   16384

// Scratch (device globals are the sanctioned scratch mechanism)
__device__ __half g_xn[(size_t)TOKENS * DIN];   // layernormed x, fp16 (64 MB)
__device__ __half g_ws[(size_t)DOUT * DIN];     // sign(W), fp16 (128 MB)

__device__ __forceinline__ uint32_t smem_u32(const void* p) {
    uint32_t a;
    asm("{ .reg .u64 t; cvta.to.shared.u64 t, %1; cvt.u32.u64 %0, t; }"
        : "=r"(a) : "l"(p));
    return a;
}

__device__ __forceinline__ float sgnf(float a) {
    return (a > 0.f) ? 1.f : ((a < 0.f) ? -1.f : 0.f);
}

__device__ __forceinline__ float4 ldcs4(const float4* p) {
    float4 v;
    asm volatile("ld.global.cs.v4.f32 {%0,%1,%2,%3}, [%4];"
                 : "=f"(v.x), "=f"(v.y), "=f"(v.z), "=f"(v.w) : "l"(p));
    return v;
}

// ---------------------------------------------------------------------------
// Kernel 1 (fused prep): per-block layernorm row, then grid-stride sign(W).
// Streaming (evict-first) reads: x and w are read exactly once.
// ---------------------------------------------------------------------------
__global__ __launch_bounds__(256) void prep_kernel(const float* __restrict__ x,
                                                   const float4* __restrict__ w) {
    int row = blockIdx.x;
    {
        const float4* xr = (const float4*)(x + (size_t)row * DIN);
        float4 v[4];
        float s = 0.f, ss = 0.f;
#pragma unroll
        for (int i = 0; i < 4; i++) {
            v[i] = ldcs4(xr + threadIdx.x + i * 256);
            s  += v[i].x + v[i].y + v[i].z + v[i].w;
            ss += v[i].x * v[i].x + v[i].y * v[i].y + v[i].z * v[i].z + v[i].w * v[i].w;
        }
#pragma unroll
        for (int o = 16; o > 0; o >>= 1) {
            s  += __shfl_xor_sync(0xFFFFFFFFu, s, o);
            ss += __shfl_xor_sync(0xFFFFFFFFu, ss, o);
        }
        __shared__ float sh[18];
        int wid = threadIdx.x >> 5, lane = threadIdx.x & 31;
        if (lane == 0) { sh[wid] = s; sh[8 + wid] = ss; }
        __syncthreads();
        if (threadIdx.x == 0) {
            float S = 0.f, SS = 0.f;
#pragma unroll
            for (int i = 0; i < 8; i++) { S += sh[i]; SS += sh[8 + i]; }
            float mean = S * (1.f / DIN);
            float var  = fmaxf((SS - S * mean) * (1.f / (DIN - 1)), 0.f);
            sh[16] = mean;
            sh[17] = 1.f / (sqrtf(var) + 1e-5f);
        }
        __syncthreads();
        float mean = sh[16], inv = sh[17];
        __half2* orow = (__half2*)(g_xn + (size_t)row * DIN);
#pragma unroll
        for (int i = 0; i < 4; i++) {
            int j = threadIdx.x + i * 256;
            orow[j * 2 + 0] = __floats2half2_rn((v[i].x - mean) * inv, (v[i].y - mean) * inv);
            orow[j * 2 + 1] = __floats2half2_rn((v[i].z - mean) * inv, (v[i].w - mean) * inv);
        }
    }
    // sign(W): grid-stride, 2 independent loads per iteration for MLP
    {
        size_t total = (size_t)DOUT * DIN / 4;   // 16M float4 groups
        size_t stride = (size_t)gridDim.x * 256;
        __half2* o = (__half2*)g_ws;
        size_t i = (size_t)blockIdx.x * 256 + threadIdx.x;
        for (; i + stride < total; i += 2 * stride) {
            float4 v0 = ldcs4(w + i);
            float4 v1 = ldcs4(w + i + stride);
            o[2 * i + 0] = __floats2half2_rn(sgnf(v0.x), sgnf(v0.y));
            o[2 * i + 1] = __floats2half2_rn(sgnf(v0.z), sgnf(v0.w));
            o[2 * (i + stride) + 0] = __floats2half2_rn(sgnf(v1.x), sgnf(v1.y));
            o[2 * (i + stride) + 1] = __floats2half2_rn(sgnf(v1.z), sgnf(v1.w));
        }
        if (i < total) {
            float4 v0 = ldcs4(w + i);
            o[2 * i + 0] = __floats2half2_rn(sgnf(v0.x), sgnf(v0.y));
            o[2 * i + 1] = __floats2half2_rn(sgnf(v0.z), sgnf(v0.w));
        }
    }
}

// ---------------------------------------------------------------------------
// Kernel 2: persistent HMMA GEMM (R13 structure, UNCHANGED). CTA = 128
//   threads (2x2 warps), tile 128x128x64, warp tile 64x64, 3-stage cp.async,
//   2 CTAs/SM. Two 8-deep cp.async bursts per kc (A after kk0 LDSMs,
//   B after kk1 LDSMs, commit at kk1); prefetch continuous across tiles;
//   stage idx = mod-3 counters. Epilogue bias hoisted per tile.
// ---------------------------------------------------------------------------
constexpr int BM = 128, BN = 128, BK = 64;
constexpr int NK = DIN / BK;                 // 64 K-chunks per tile
constexpr int ASZ = BM * BK * 2;             // 16 KB
constexpr int BSZ = BN * BK * 2;             // 16 KB
constexpr int STG = ASZ + BSZ;               // 32 KB per stage
constexpr int NSTAGE = 3;
constexpr int SMEM_TOTAL = NSTAGE * STG;     // 96 KB (x2 CTAs = 192 KB/SM)
constexpr int CTA_THREADS = 128;
constexpr int NTILES = (TOKENS / BM) * (DOUT / BN);   // 8192

__device__ __forceinline__ void ldmx4(uint32_t* r, uint32_t addr) {
    asm volatile("ldmatrix.sync.aligned.m8n8.x4.shared.b16 {%0,%1,%2,%3}, [%4];"
                 : "=r"(r[0]), "=r"(r[1]), "=r"(r[2]), "=r"(r[3]) : "r"(addr));
}

__device__ __forceinline__ void mma16816(float* c, const uint32_t* a, const uint32_t* b) {
    asm volatile(
        "mma.sync.aligned.m16n8k16.row.col.f32.f16.f16.f32 "
        "{%0,%1,%2,%3}, {%4,%5,%6,%7}, {%8,%9}, {%0,%1,%2,%3};"
        : "+f"(c[0]), "+f"(c[1]), "+f"(c[2]), "+f"(c[3])
        : "r"(a[0]), "r"(a[1]), "r"(a[2]), "r"(a[3]), "r"(b[0]), "r"(b[1]));
}

__device__ __forceinline__ void load_stage_A(uint32_t sb, int buf, int kc,
                                             const __half* Ag, int tid) {
    uint32_t base = sb + buf * STG;
    int k0 = kc * BK;
#pragma unroll
    for (int i = 0; i < 8; i++) {
        int g = tid + i * CTA_THREADS;
        int row = g >> 3, c = g & 7;
        const void* src = Ag + (size_t)row * DIN + k0 + c * 8;
        uint32_t dst = base + row * 128 + ((c ^ (row & 7)) << 4);
        asm volatile("cp.async.cg.shared.global [%0], [%1], 16;" :: "r"(dst), "l"(src) : "memory");
    }
}

__device__ __forceinline__ void load_stage_B(uint32_t sb, int buf, int kc,
                                             const __half* Bg, int tid) {
    uint32_t base = sb + buf * STG + ASZ;
    int k0 = kc * BK;
#pragma unroll
    for (int i = 0; i < 8; i++) {
        int g = tid + i * CTA_THREADS;
        int row = g >> 3, c = g & 7;
        const void* src = Bg + (size_t)row * DIN + k0 + c * 8;
        uint32_t dst = base + row * 128 + ((c ^ (row & 7)) << 4);
        asm volatile("cp.async.cg.shared.global [%0], [%1], 16;" :: "r"(dst), "l"(src) : "memory");
    }
}

__global__ __launch_bounds__(CTA_THREADS, 2)
void gemm_kernel(const float* __restrict__ bias, float* __restrict__ out) {
    extern __shared__ char smem[];
    uint32_t sb = smem_u32(smem);
    int tid = threadIdx.x, wid = tid >> 5, lane = tid & 31;
    int wm = wid & 1;        // 2 warps along M (64 rows each)
    int wn = wid >> 1;       // 2 warps along N (64 cols each)
    int bid = blockIdx.x, nblk = gridDim.x;

    // A ldmatrix lane address components
    int arow = wm * 64 + (lane & 15);
    int ahalf = lane >> 4;
    int axm = arow & 7;
    uint32_t aoff = (uint32_t)arow * 128;
    // B ldmatrix lane address components
    int bgp = lane >> 3, bj = lane & 7;
    int brow = wn * 64 + ((bgp >> 1) << 3) + bj;
    int bhalf = bgp & 1;
    int bxm = brow & 7;
    uint32_t boff = (uint32_t)brow * 128;

    int ntile_cta = (NTILES - bid + nblk - 1) / nblk;
    if (ntile_cta <= 0) return;

    // stage counters (increment-mod-3, no division in the loop)
    int buf = 0;        // stage holding current kc's data
    int pbuf = 2;       // stage that prefetch (kc+2) writes into

    // prologue: fill stages 0,1 with tile0 kc0,kc1
    {
        const __half* Ag0 = g_xn + (size_t)(bid & 63) * BM * DIN;
        const __half* Bg0 = g_ws + (size_t)(bid >> 6) * BN * DIN;
        load_stage_A(sb, 0, 0, Ag0, tid);
        load_stage_B(sb, 0, 0, Bg0, tid);
        asm volatile("cp.async.commit_group;" ::: "memory");
        load_stage_A(sb, 1, 1, Ag0, tid);
        load_stage_B(sb, 1, 1, Bg0, tid);
        asm volatile("cp.async.commit_group;" ::: "memory");
    }

    for (int it = 0; it < ntile_cta; it++) {
        int t = bid + it * nblk;
        int m0 = (t & 63) * BM;
        int n0 = (t >> 6) * BN;
        const __half* Ag = g_xn + (size_t)(t & 63) * BM * DIN;
        const __half* Bg = g_ws + (size_t)(t >> 6) * BN * DIN;

        // next-tile pointers, computed ONCE per tile
        bool has_next = (it + 1 < ntile_cta);
        int tn = t + nblk;
        if (tn >= NTILES) tn = t;                // clamp (unused when !has_next)
        const __half* AgN = g_xn + (size_t)(tn & 63) * BM * DIN;
        const __half* BgN = g_ws + (size_t)(tn >> 6) * BN * DIN;

        float acc[4][8][4];
#pragma unroll
        for (int i = 0; i < 4; i++)
#pragma unroll
            for (int j = 0; j < 8; j++)
#pragma unroll
                for (int q = 0; q < 4; q++) acc[i][j][q] = 0.f;

        for (int kc = 0; kc < NK; kc++) {
            asm volatile("cp.async.wait_group 1;" ::: "memory");
            __syncthreads();

            uint32_t abase = sb + buf * STG + aoff;
            uint32_t bbase = sb + buf * STG + ASZ + boff;

            // prefetch routing: common case = current tile
            bool pf_cur = (kc < NK - 2);
            bool pf_nxt = (!pf_cur) && has_next;
            int pkc_n = kc + 2 - NK;             // 0 or 1 in the peel region

            uint32_t afr[4][4], bfr[4][4];

            // kk=0 LDSMs, then A-prefetch burst, then kk=0 MMAs
#pragma unroll
            for (int mt = 0; mt < 4; mt++)
                ldmx4(afr[mt], abase + mt * 2048 + ((ahalf ^ axm) << 4));
#pragma unroll
            for (int np = 0; np < 4; np++)
                ldmx4(bfr[np], bbase + np * 2048 + ((bhalf ^ bxm) << 4));

            if (pf_cur)      load_stage_A(sb, pbuf, kc + 2, Ag, tid);
            else if (pf_nxt) load_stage_A(sb, pbuf, pkc_n, AgN, tid);

#pragma unroll
            for (int mt = 0; mt < 4; mt++)
#pragma unroll
                for (int nt = 0; nt < 8; nt++)
                    mma16816(acc[mt][nt], afr[mt], &bfr[nt >> 1][(nt & 1) * 2]);

            // kk=1 LDSMs, then B-prefetch burst + commit, then kk=1 MMAs
#pragma unroll
            for (int mt = 0; mt < 4; mt++)
                ldmx4(afr[mt], abase + mt * 2048 + (((2 + ahalf) ^ axm) << 4));
#pragma unroll
            for (int np = 0; np < 4; np++)
                ldmx4(bfr[np], bbase + np * 2048 + (((2 + bhalf) ^ bxm) << 4));

            if (pf_cur)      load_stage_B(sb, pbuf, kc + 2, Bg, tid);
            else if (pf_nxt) load_stage_B(sb, pbuf, pkc_n, BgN, tid);
            asm volatile("cp.async.commit_group;" ::: "memory");

#pragma unroll
            for (int mt = 0; mt < 4; mt++)
#pragma unroll
                for (int nt = 0; nt < 8; nt++)
                    mma16816(acc[mt][nt], afr[mt], &bfr[nt >> 1][(nt & 1) * 2]);

            // kk = 2..3
#pragma unroll
            for (int kk = 2; kk < 4; kk++) {
#pragma unroll
                for (int mt = 0; mt < 4; mt++) {
                    int ch = kk * 2 + ahalf;
                    ldmx4(afr[mt], abase + mt * 2048 + ((ch ^ axm) << 4));
                }
#pragma unroll
                for (int np = 0; np < 4; np++) {
                    int ch = kk * 2 + bhalf;
                    ldmx4(bfr[np], bbase + np * 2048 + ((ch ^ bxm) << 4));
                }
#pragma unroll
                for (int mt = 0; mt < 4; mt++)
#pragma unroll
                    for (int nt = 0; nt < 8; nt++)
                        mma16816(acc[mt][nt], afr[mt], &bfr[nt >> 1][(nt & 1) * 2]);
            }

            // advance stage counters (SEL, no division)
            buf  = (buf == NSTAGE - 1)  ? 0 : buf + 1;
            pbuf = (pbuf == NSTAGE - 1) ? 0 : pbuf + 1;
        }

        // epilogue: bias hoisted (8 loads/thread/tile), streaming stores
        float2 bv[8];
#pragma unroll
        for (int nt = 0; nt < 8; nt++) {
            int col = n0 + wn * 64 + nt * 8 + 2 * (lane & 3);
            asm volatile("ld.global.nc.v2.f32 {%0,%1}, [%2];"
                         : "=f"(bv[nt].x), "=f"(bv[nt].y) : "l"(bias + col));
        }
#pragma unroll
        for (int mt = 0; mt < 4; mt++) {
#pragma unroll
            for (int nt = 0; nt < 8; nt++) {
                int row = m0 + wm * 64 + mt * 16 + (lane >> 2);
                int col = n0 + wn * 64 + nt * 8 + 2 * (lane & 3);
                float* p0 = out + (size_t)row * DOUT + col;
                float* p1 = out + (size_t)(row + 8) * DOUT + col;
                asm volatile("st.global.cs.v2.f32 [%0], {%1,%2};"
                             :: "l"(p0), "f"(acc[mt][nt][0] + bv[nt].x), "f"(acc[mt][nt][1] + bv[nt].y)
                             : "memory");
                asm volatile("st.global.cs.v2.f32 [%0], {%1,%2};"
                             :: "l"(p1), "f"(acc[mt][nt][2] + bv[nt].x), "f"(acc[mt][nt][3] + bv[nt].y)
                             : "memory");
            }
        }
    }
}

// ---------------------------------------------------------------------------
// kernel_launch
// ---------------------------------------------------------------------------
extern "C" void kernel_launch(void* const* d_in, const int* in_sizes, int n_in,
                              void* d_out, int out_size) {
    const float* x    = (const float*)d_in[0];
    const float* w    = (const float*)d_in[1];
    const float* bias = (const float*)d_in[2];
    float* out = (float*)d_out;

    static int nsm = 0;
    if (nsm == 0) {
        cudaDeviceGetAttribute(&nsm, cudaDevAttrMultiProcessorCount, 0);
        cudaFuncSetAttribute(gemm_kernel, cudaFuncAttributeMaxDynamicSharedMemorySize, SMEM_TOTAL);
    }

    prep_kernel<<<TOKENS, 256>>>(x, (const float4*)w);
    gemm_kernel<<<2 * nsm, CTA_THREADS, SMEM_TOTAL>>>(bias, out);
}